// round 11
// baseline (speedup 1.0000x reference)
#include <cuda_runtime.h>
#include <cuda_bf16.h>
#include <cstdint>

// Problem constants: B=4, C=128, W=H=64
#define NB  4
#define NCH 64
#define ND  8
#define NN  4096
#define MT  32      // query tile -> grid 512
#define NT  64      // key tile
#define EP  72      // e-tile pad (bf16 units)
#define VP  72      // v-tile pad (bf16 units)

// Scratch (no cudaMalloc allowed)
__device__ __align__(16) float         g_p2t[NB * NN * ND];   // tf32-rounded
__device__ __align__(16) float         g_p3t[NB * NN * ND];   // tf32-rounded
__device__ __align__(16) __nv_bfloat16 g_v3b[NB * NN * NCH];  // [b][n][c] bf16

__device__ __forceinline__ float to_tf32(float x) {
    unsigned u;
    asm("cvt.rna.tf32.f32 %0, %1;" : "=r"(u) : "f"(x));
    return __uint_as_float(u);
}
__device__ __forceinline__ unsigned pk_bf16x2(float lo, float hi) {
    unsigned r;
    asm("cvt.rn.bf16x2.f32 %0, %1, %2;" : "=r"(r) : "f"(hi), "f"(lo));
    return r;
}
__device__ __forceinline__ void mma_tf32(float* c,
                                         unsigned a0, unsigned a1, unsigned a2, unsigned a3,
                                         unsigned b0, unsigned b1)
{
    asm volatile(
        "mma.sync.aligned.m16n8k8.row.col.f32.tf32.tf32.f32 "
        "{%0,%1,%2,%3}, {%4,%5,%6,%7}, {%8,%9}, {%0,%1,%2,%3};"
        : "+f"(c[0]), "+f"(c[1]), "+f"(c[2]), "+f"(c[3])
        : "r"(a0), "r"(a1), "r"(a2), "r"(a3), "r"(b0), "r"(b1));
}
__device__ __forceinline__ void mma_bf16(float* c,
                                         unsigned a0, unsigned a1, unsigned a2, unsigned a3,
                                         unsigned b0, unsigned b1)
{
    asm volatile(
        "mma.sync.aligned.m16n8k16.row.col.f32.bf16.bf16.f32 "
        "{%0,%1,%2,%3}, {%4,%5,%6,%7}, {%8,%9}, {%0,%1,%2,%3};"
        : "+f"(c[0]), "+f"(c[1]), "+f"(c[2]), "+f"(c[3])
        : "r"(a0), "r"(a1), "r"(a2), "r"(a3), "r"(b0), "r"(b1));
}
__device__ __forceinline__ void ldsm_x2_trans(unsigned& r0, unsigned& r1, uint32_t addr)
{
    asm volatile("ldmatrix.sync.aligned.m8n8.x2.trans.shared.b16 {%0,%1}, [%2];"
                 : "=r"(r0), "=r"(r1) : "r"(addr));
}

// ---------------------------------------------------------------------------
// K1: projections, z-split. z=0: p2,p3 (tf32) + v[0:32]; z=1: v[32:64].
// ---------------------------------------------------------------------------
__global__ void proj_kernel(const float* __restrict__ x,
                            const float* __restrict__ wq2, const float* __restrict__ bq2,
                            const float* __restrict__ wq3, const float* __restrict__ bq3,
                            const float* __restrict__ wv3, const float* __restrict__ bv3)
{
    __shared__ float s_wq2[ND * NCH];
    __shared__ float s_wq3[ND * NCH];
    __shared__ float s_wv3[32 * NCH];    // this z-half's rows of wv3
    __shared__ float s_b[2 * ND + 32];

    const int tid = threadIdx.x;
    const int z   = blockIdx.z;
    const int co0 = z * 32;              // v output-channel base
    if (z == 0) {
        for (int i = tid; i < ND * NCH; i += 128) { s_wq2[i] = wq2[i]; s_wq3[i] = wq3[i]; }
        if (tid < ND)           s_b[tid] = bq2[tid];
        else if (tid < 2 * ND)  s_b[tid] = bq3[tid - ND];
    }
    for (int i = tid; i < 32 * NCH; i += 128) s_wv3[i] = wv3[co0 * NCH + i];
    if (tid < 32) s_b[2 * ND + tid] = bv3[co0 + tid];
    __syncthreads();

    const int b = blockIdx.y;
    const int n = blockIdx.x * 128 + tid;
    const float* xb = x + (size_t)b * (2 * NCH) * NN;

    float v[32];
#pragma unroll
    for (int c = 0; c < 32; c++) v[c] = s_b[2 * ND + c];

    if (z == 0) {
        float p2[ND], p3[ND];
#pragma unroll
        for (int d = 0; d < ND; d++) { p2[d] = s_b[d]; p3[d] = s_b[ND + d]; }
        for (int c = 0; c < NCH; c++) {
            const float x3v = xb[c * NN + n];
            const float x2v = xb[(NCH + c) * NN + n];
#pragma unroll
            for (int d = 0; d < ND; d++) {
                p2[d] = fmaf(s_wq2[d * NCH + c], x2v, p2[d]);
                p3[d] = fmaf(s_wq3[d * NCH + c], x3v, p3[d]);
            }
#pragma unroll
            for (int o = 0; o < 32; o++)
                v[o] = fmaf(s_wv3[o * NCH + c], x3v, v[o]);
        }
        float* o2 = g_p2t + ((size_t)b * NN + n) * ND;
        float* o3 = g_p3t + ((size_t)b * NN + n) * ND;
#pragma unroll
        for (int d = 0; d < ND; d++) { o2[d] = to_tf32(p2[d]); o3[d] = to_tf32(p3[d]); }
    } else {
        for (int c = 0; c < NCH; c++) {
            const float x3v = xb[c * NN + n];
#pragma unroll
            for (int o = 0; o < 32; o++)
                v[o] = fmaf(s_wv3[o * NCH + c], x3v, v[o]);
        }
    }
    __nv_bfloat16* ov = g_v3b + ((size_t)b * NN + n) * NCH + co0;
#pragma unroll
    for (int c = 0; c < 32; c++) ov[c] = __float2bfloat16(v[c]);
}

// ---------------------------------------------------------------------------
// K2: single-pass dual attention per (batch, 32-query tile). 256 threads.
//  Warp w: wm=(w&1)*16 (m-block); wq=w>>1 (quarter): score keys n=wq*16+..,
//  out channels c=wq*16+..  Score B-frags via coalesced LDG from L2.
// ---------------------------------------------------------------------------
__global__ __launch_bounds__(256, 3) void att_kernel(const float* __restrict__ x,
                                                     const float* __restrict__ g2p,
                                                     const float* __restrict__ g3p,
                                                     float* __restrict__ out)
{
    __shared__ __align__(16) __nv_bfloat16 s_v[NT * VP];      // [n][c] 9216B
    __shared__ __align__(16) __nv_bfloat16 s_e[2][MT * EP];   // e32,e33 [m][n]; aliased s_red
    __shared__ __align__(16) float s_z32[4][MT];
    __shared__ __align__(16) float s_z33[4][MT];
    __shared__ __align__(16) float s_f32[MT];
    __shared__ __align__(16) float s_f33[MT];

    const int tid  = threadIdx.x;
    const int b    = blockIdx.y;
    const int m0   = blockIdx.x * MT;
    const int warp = tid >> 5;
    const int lane = tid & 31;
    const int g8   = lane >> 2;
    const int l4   = lane & 3;
    const int wm   = (warp & 1) * 16;
    const int wq   = warp >> 1;         // quarter 0..3
    const int wn   = wq * 16;           // score key base within tile
    const int wc   = wq * 16;           // out channel base

    const float g2 = *g2p;
    const float g3 = *g3p;

    const float* pb2 = g_p2t + (size_t)b * NN * ND;
    const float* pb3 = g_p3t + (size_t)b * NN * ND;
    const uint4* vgb = (const uint4*)(g_v3b + (size_t)b * NN * NCH);

    // q A-fragment (fixed; already tf32-rounded)
    const float* qb = g_p3t + ((size_t)b * NN + m0) * ND;
    const unsigned aq0 = __float_as_uint(qb[(wm + g8) * ND + l4]);
    const unsigned aq1 = __float_as_uint(qb[(wm + g8 + 8) * ND + l4]);
    const unsigned aq2 = __float_as_uint(qb[(wm + g8) * ND + l4 + 4]);
    const unsigned aq3 = __float_as_uint(qb[(wm + g8 + 8) * ND + l4 + 4]);

    float acc32[2][4], acc33[2][4];
#pragma unroll
    for (int ct = 0; ct < 2; ct++)
#pragma unroll
        for (int j = 0; j < 4; j++) { acc32[ct][j] = 0.f; acc33[ct][j] = 0.f; }
    float sum32a = 0.f, sum32b = 0.f, sum33a = 0.f, sum33b = 0.f;

    // prefetch v(0) and score key-frags(0)
    uint4 vr0 = vgb[tid * 2];
    uint4 vr1 = vgb[tid * 2 + 1];
    float f20[2], f21[2], f30[2], f31[2];
#pragma unroll
    for (int i = 0; i < 2; i++) {
        const int row = (wn + i * 8 + g8) * ND;
        f20[i] = pb2[row + l4];
        f21[i] = pb2[row + l4 + 4];
        f30[i] = pb3[row + l4];
        f31[i] = pb3[row + l4 + 4];
    }

    for (int t = 0; t < NN / NT; t++) {
        // stage v(t)
        {
            const int fi = tid * 2;
            *(uint4*)&s_v[(fi >> 3) * VP + (fi & 7) * 8]             = vr0;
            *(uint4*)&s_v[((fi + 1) >> 3) * VP + ((fi + 1) & 7) * 8] = vr1;
        }
        // scores (tf32 mma) -> exp -> Z partials + bf16 e-tiles
#pragma unroll
        for (int i = 0; i < 2; i++) {
            const int n0 = wn + i * 8;
            float c2[4] = {0.f, 0.f, 0.f, 0.f};
            float c3[4] = {0.f, 0.f, 0.f, 0.f};
            mma_tf32(c2, aq0, aq1, aq2, aq3,
                     __float_as_uint(f20[i]), __float_as_uint(f21[i]));
            mma_tf32(c3, aq0, aq1, aq2, aq3,
                     __float_as_uint(f30[i]), __float_as_uint(f31[i]));
            const float e0 = __expf(c2[0]), e1 = __expf(c2[1]);
            const float e2 = __expf(c2[2]), e3 = __expf(c2[3]);
            sum32a += e0 + e1; sum32b += e2 + e3;
            *(unsigned*)&s_e[0][(wm + g8) * EP + n0 + 2 * l4]     = pk_bf16x2(e0, e1);
            *(unsigned*)&s_e[0][(wm + g8 + 8) * EP + n0 + 2 * l4] = pk_bf16x2(e2, e3);
            const float f0 = __expf(c3[0]), f1 = __expf(c3[1]);
            const float f2 = __expf(c3[2]), f3 = __expf(c3[3]);
            sum33a += f0 + f1; sum33b += f2 + f3;
            *(unsigned*)&s_e[1][(wm + g8) * EP + n0 + 2 * l4]     = pk_bf16x2(f0, f1);
            *(unsigned*)&s_e[1][(wm + g8 + 8) * EP + n0 + 2 * l4] = pk_bf16x2(f2, f3);
        }
        // prefetch tile t+1 (lands during gemm)
        if (t + 1 < NN / NT) {
            vr0 = vgb[(t + 1) * 512 + tid * 2];
            vr1 = vgb[(t + 1) * 512 + tid * 2 + 1];
#pragma unroll
            for (int i = 0; i < 2; i++) {
                const int row = ((t + 1) * NT + wn + i * 8 + g8) * ND;
                f20[i] = pb2[row + l4];
                f21[i] = pb2[row + l4 + 4];
                f30[i] = pb3[row + l4];
                f31[i] = pb3[row + l4 + 4];
            }
        }
        __syncthreads();   // e(t), v(t) visible

        // out GEMMs (bf16): acc += E^T(16m x 64n) * V(64n x 16c), both atts
#pragma unroll
        for (int kc = 0; kc < 4; kc++) {
            const int kn = kc * 16;
            const unsigned a20 = *(const unsigned*)&s_e[0][(wm + g8) * EP + kn + 2 * l4];
            const unsigned a21 = *(const unsigned*)&s_e[0][(wm + g8 + 8) * EP + kn + 2 * l4];
            const unsigned a22 = *(const unsigned*)&s_e[0][(wm + g8) * EP + kn + 2 * l4 + 8];
            const unsigned a23 = *(const unsigned*)&s_e[0][(wm + g8 + 8) * EP + kn + 2 * l4 + 8];
            const unsigned a30 = *(const unsigned*)&s_e[1][(wm + g8) * EP + kn + 2 * l4];
            const unsigned a31 = *(const unsigned*)&s_e[1][(wm + g8 + 8) * EP + kn + 2 * l4];
            const unsigned a32 = *(const unsigned*)&s_e[1][(wm + g8) * EP + kn + 2 * l4 + 8];
            const unsigned a33 = *(const unsigned*)&s_e[1][(wm + g8 + 8) * EP + kn + 2 * l4 + 8];
#pragma unroll
            for (int ct = 0; ct < 2; ct++) {
                const int c0 = wc + ct * 8;
                unsigned b0, b1;
                const uint32_t addr = (uint32_t)__cvta_generic_to_shared(
                    &s_v[(kn + (lane & 15)) * VP + c0]);
                ldsm_x2_trans(b0, b1, addr);
                mma_bf16(acc32[ct], a20, a21, a22, a23, b0, b1);
                mma_bf16(acc33[ct], a30, a31, a32, a33, b0, b1);
            }
        }
        __syncthreads();   // e/v consumed; safe to restage
    }

    // ---------------- Z reduction + normalization factors ----------------
    sum32a += __shfl_xor_sync(0xffffffffu, sum32a, 1);
    sum32a += __shfl_xor_sync(0xffffffffu, sum32a, 2);
    sum32b += __shfl_xor_sync(0xffffffffu, sum32b, 1);
    sum32b += __shfl_xor_sync(0xffffffffu, sum32b, 2);
    sum33a += __shfl_xor_sync(0xffffffffu, sum33a, 1);
    sum33a += __shfl_xor_sync(0xffffffffu, sum33a, 2);
    sum33b += __shfl_xor_sync(0xffffffffu, sum33b, 1);
    sum33b += __shfl_xor_sync(0xffffffffu, sum33b, 2);
    if (l4 == 0) {
        s_z32[wq][wm + g8]     = sum32a;
        s_z32[wq][wm + g8 + 8] = sum32b;
        s_z33[wq][wm + g8]     = sum33a;
        s_z33[wq][wm + g8 + 8] = sum33b;
    }
    __syncthreads();
    if (tid < MT) {
        s_f32[tid] = g2 / (s_z32[0][tid] + s_z32[1][tid] + s_z32[2][tid] + s_z32[3][tid]);
        s_f33[tid] = g3 / (s_z33[0][tid] + s_z33[1][tid] + s_z33[2][tid] + s_z33[3][tid]);
    }
    __syncthreads();

    // ---------------- scale + stage + coalesced write ----------------
    float* s_red = (float*)s_e;              // [32 m][72] fp32 (overlays s_e)
    const float f2a = s_f32[wm + g8],     f3a = s_f33[wm + g8];
    const float f2b = s_f32[wm + g8 + 8], f3b = s_f33[wm + g8 + 8];
#pragma unroll
    for (int ct = 0; ct < 2; ct++) {
        const int c = wc + ct * 8 + 2 * l4;
        float2 lo, hi;
        lo.x = f2a * acc32[ct][0] + f3a * acc33[ct][0];
        lo.y = f2a * acc32[ct][1] + f3a * acc33[ct][1];
        hi.x = f2b * acc32[ct][2] + f3b * acc33[ct][2];
        hi.y = f2b * acc32[ct][3] + f3b * acc33[ct][3];
        *(float2*)&s_red[(wm + g8) * 72 + c]     = lo;
        *(float2*)&s_red[(wm + g8 + 8) * 72 + c] = hi;
    }
    __syncthreads();
    {
        const float* xb = x + (size_t)b * (2 * NCH) * NN;   // x3 = channels 0..63
        float* ob = out + (size_t)b * NCH * NN;
#pragma unroll
        for (int j = 0; j < 2; j++) {
            const int idx = tid + j * 256;   // 0..511 = 64c x 8 float4-of-m
            const int c   = idx >> 3;
            const int mf  = idx & 7;
            const float4 xv = *(const float4*)(xb + (size_t)c * NN + m0 + mf * 4);
            float4 o;
            o.x = s_red[(mf * 4 + 0) * 72 + c] + xv.x;
            o.y = s_red[(mf * 4 + 1) * 72 + c] + xv.y;
            o.z = s_red[(mf * 4 + 2) * 72 + c] + xv.z;
            o.w = s_red[(mf * 4 + 3) * 72 + c] + xv.w;
            *(float4*)(ob + (size_t)c * NN + m0 + mf * 4) = o;
        }
    }
}

extern "C" void kernel_launch(void* const* d_in, const int* in_sizes, int n_in,
                              void* d_out, int out_size)
{
    const float* x   = (const float*)d_in[0];
    const float* wq2 = (const float*)d_in[1];
    const float* bq2 = (const float*)d_in[2];
    const float* wq3 = (const float*)d_in[3];
    const float* bq3 = (const float*)d_in[4];
    const float* wv3 = (const float*)d_in[5];
    const float* bv3 = (const float*)d_in[6];
    const float* g2  = (const float*)d_in[7];
    const float* g3  = (const float*)d_in[8];
    float* out = (float*)d_out;

    proj_kernel<<<dim3(NN / 128, NB, 2), 128>>>(x, wq2, bq2, wq3, bq3, wv3, bv3);
    att_kernel<<<dim3(NN / MT, NB), 256>>>(x, g2, g3, out);
}

// round 12
// speedup vs baseline: 1.3336x; 1.3336x over previous
#include <cuda_runtime.h>
#include <cuda_bf16.h>
#include <cstdint>

// Problem constants: B=4, C=128, W=H=64
#define NB  4
#define NCH 64
#define ND  8
#define NN  4096
#define MT  64      // query tile -> grid 256
#define NT  64      // key tile
#define VP  72      // v-tile pad (bf16 units)

// Scratch (no cudaMalloc allowed)
__device__ __align__(16) float         g_p2t[NB * NN * ND];   // tf32-rounded
__device__ __align__(16) float         g_p3t[NB * NN * ND];   // tf32-rounded
__device__ __align__(16) __nv_bfloat16 g_v3b[NB * NN * NCH];  // [b][n][c] bf16

__device__ __forceinline__ float to_tf32(float x) {
    unsigned u;
    asm("cvt.rna.tf32.f32 %0, %1;" : "=r"(u) : "f"(x));
    return __uint_as_float(u);
}
__device__ __forceinline__ unsigned pk_bf16x2(float lo, float hi) {
    unsigned r;
    asm("cvt.rn.bf16x2.f32 %0, %1, %2;" : "=r"(r) : "f"(hi), "f"(lo));
    return r;
}
__device__ __forceinline__ void mma_tf32(float* c,
                                         unsigned a0, unsigned a1, unsigned a2, unsigned a3,
                                         unsigned b0, unsigned b1)
{
    asm volatile(
        "mma.sync.aligned.m16n8k8.row.col.f32.tf32.tf32.f32 "
        "{%0,%1,%2,%3}, {%4,%5,%6,%7}, {%8,%9}, {%0,%1,%2,%3};"
        : "+f"(c[0]), "+f"(c[1]), "+f"(c[2]), "+f"(c[3])
        : "r"(a0), "r"(a1), "r"(a2), "r"(a3), "r"(b0), "r"(b1));
}
__device__ __forceinline__ void mma_bf16(float* c,
                                         unsigned a0, unsigned a1, unsigned a2, unsigned a3,
                                         unsigned b0, unsigned b1)
{
    asm volatile(
        "mma.sync.aligned.m16n8k16.row.col.f32.bf16.bf16.f32 "
        "{%0,%1,%2,%3}, {%4,%5,%6,%7}, {%8,%9}, {%0,%1,%2,%3};"
        : "+f"(c[0]), "+f"(c[1]), "+f"(c[2]), "+f"(c[3])
        : "r"(a0), "r"(a1), "r"(a2), "r"(a3), "r"(b0), "r"(b1));
}
__device__ __forceinline__ void ldsm_x2_trans(unsigned& r0, unsigned& r1, uint32_t addr)
{
    asm volatile("ldmatrix.sync.aligned.m8n8.x2.trans.shared.b16 {%0,%1}, [%2];"
                 : "=r"(r0), "=r"(r1) : "r"(addr));
}

// ---------------------------------------------------------------------------
// K1: projections, z-split. z=0: p2,p3 (tf32) + v[0:32]; z=1: v[32:64].
// ---------------------------------------------------------------------------
__global__ void proj_kernel(const float* __restrict__ x,
                            const float* __restrict__ wq2, const float* __restrict__ bq2,
                            const float* __restrict__ wq3, const float* __restrict__ bq3,
                            const float* __restrict__ wv3, const float* __restrict__ bv3)
{
    __shared__ float s_wq2[ND * NCH];
    __shared__ float s_wq3[ND * NCH];
    __shared__ float s_wv3[32 * NCH];
    __shared__ float s_b[2 * ND + 32];

    const int tid = threadIdx.x;
    const int z   = blockIdx.z;
    const int co0 = z * 32;
    if (z == 0) {
        for (int i = tid; i < ND * NCH; i += 128) { s_wq2[i] = wq2[i]; s_wq3[i] = wq3[i]; }
        if (tid < ND)           s_b[tid] = bq2[tid];
        else if (tid < 2 * ND)  s_b[tid] = bq3[tid - ND];
    }
    for (int i = tid; i < 32 * NCH; i += 128) s_wv3[i] = wv3[co0 * NCH + i];
    if (tid < 32) s_b[2 * ND + tid] = bv3[co0 + tid];
    __syncthreads();

    const int b = blockIdx.y;
    const int n = blockIdx.x * 128 + tid;
    const float* xb = x + (size_t)b * (2 * NCH) * NN;

    float v[32];
#pragma unroll
    for (int c = 0; c < 32; c++) v[c] = s_b[2 * ND + c];

    if (z == 0) {
        float p2[ND], p3[ND];
#pragma unroll
        for (int d = 0; d < ND; d++) { p2[d] = s_b[d]; p3[d] = s_b[ND + d]; }
        for (int c = 0; c < NCH; c++) {
            const float x3v = xb[c * NN + n];
            const float x2v = xb[(NCH + c) * NN + n];
#pragma unroll
            for (int d = 0; d < ND; d++) {
                p2[d] = fmaf(s_wq2[d * NCH + c], x2v, p2[d]);
                p3[d] = fmaf(s_wq3[d * NCH + c], x3v, p3[d]);
            }
#pragma unroll
            for (int o = 0; o < 32; o++)
                v[o] = fmaf(s_wv3[o * NCH + c], x3v, v[o]);
        }
        float* o2 = g_p2t + ((size_t)b * NN + n) * ND;
        float* o3 = g_p3t + ((size_t)b * NN + n) * ND;
#pragma unroll
        for (int d = 0; d < ND; d++) { o2[d] = to_tf32(p2[d]); o3[d] = to_tf32(p3[d]); }
    } else {
        for (int c = 0; c < NCH; c++) {
            const float x3v = xb[c * NN + n];
#pragma unroll
            for (int o = 0; o < 32; o++)
                v[o] = fmaf(s_wv3[o * NCH + c], x3v, v[o]);
        }
    }
    __nv_bfloat16* ov = g_v3b + ((size_t)b * NN + n) * NCH + co0;
#pragma unroll
    for (int c = 0; c < 32; c++) ov[c] = __float2bfloat16(v[c]);
}

// ---------------------------------------------------------------------------
// K2: single-pass dual attention per (batch, 64-query tile). 256 threads.
//  Warp w: wm = (w&3)*16 (m-block); att = w>>2 (0: att32/p2-keys, 1: att33/p3).
//  Per tile: 8 tf32 score mmas over ALL 64 keys -> exp -> A-fragments stay in
//  REGISTERS -> full 64-c bf16 out-GEMM for this warp's att. One sync/tile
//  (v double-buffered). Atts merged once at the end.
// ---------------------------------------------------------------------------
__global__ __launch_bounds__(256, 2) void att_kernel(const float* __restrict__ x,
                                                     const float* __restrict__ g2p,
                                                     const float* __restrict__ g3p,
                                                     float* __restrict__ out)
{
    __shared__ __align__(16) __nv_bfloat16 s_v[2][NT * VP];   // 18432B; aliased s_red
    __shared__ __align__(16) float s_z[2][MT];
    __shared__ __align__(16) float s_f32[MT];
    __shared__ __align__(16) float s_f33[MT];

    const int tid  = threadIdx.x;
    const int b    = blockIdx.y;
    const int m0   = blockIdx.x * MT;
    const int warp = tid >> 5;
    const int lane = tid & 31;
    const int g8   = lane >> 2;
    const int l4   = lane & 3;
    const int wm   = (warp & 3) * 16;
    const int att  = warp >> 2;         // 0: att32, 1: att33

    const float* pb2 = g_p2t + (size_t)b * NN * ND;
    const float* pb3 = g_p3t + (size_t)b * NN * ND;
    const float* kb  = att ? pb3 : pb2; // this warp's key projection
    const uint4* vgb = (const uint4*)(g_v3b + (size_t)b * NN * NCH);

    // q A-fragment (fixed; tf32-rounded p3 rows of this m-block)
    const float* qb = pb3 + (size_t)m0 * ND;
    const unsigned aq0 = __float_as_uint(qb[(wm + g8) * ND + l4]);
    const unsigned aq1 = __float_as_uint(qb[(wm + g8 + 8) * ND + l4]);
    const unsigned aq2 = __float_as_uint(qb[(wm + g8) * ND + l4 + 4]);
    const unsigned aq3 = __float_as_uint(qb[(wm + g8 + 8) * ND + l4 + 4]);

    float acc[8][4];                    // 16m x 64c for this warp's att
#pragma unroll
    for (int ct = 0; ct < 8; ct++)
#pragma unroll
        for (int j = 0; j < 4; j++) acc[ct][j] = 0.f;
    float suma = 0.f, sumb = 0.f;       // row sums (rows g8 / g8+8)

    // preamble: stage v(0), prefetch v(1) + keys(0)
    uint4 vr0 = vgb[tid * 2];
    uint4 vr1 = vgb[tid * 2 + 1];
    {
        const int fi = tid * 2;
        *(uint4*)&s_v[0][(fi >> 3) * VP + (fi & 7) * 8]             = vr0;
        *(uint4*)&s_v[0][((fi + 1) >> 3) * VP + ((fi + 1) & 7) * 8] = vr1;
    }
    if (1 < NN / NT) { vr0 = vgb[512 + tid * 2]; vr1 = vgb[512 + tid * 2 + 1]; }
    float kf0[8], kf1[8];
#pragma unroll
    for (int i = 0; i < 8; i++) {
        const int row = (i * 8 + g8) * ND;
        kf0[i] = kb[row + l4];
        kf1[i] = kb[row + l4 + 4];
    }
    __syncthreads();

    for (int t = 0; t < NN / NT; t++) {
        const int cur = t & 1;
        // scores over all 64 keys -> exp -> register A-fragments
        unsigned afr[4][4];
#pragma unroll
        for (int i = 0; i < 8; i++) {
            float c[4] = {0.f, 0.f, 0.f, 0.f};
            mma_tf32(c, aq0, aq1, aq2, aq3,
                     __float_as_uint(kf0[i]), __float_as_uint(kf1[i]));
            const float e0 = __expf(c[0]), e1 = __expf(c[1]);
            const float e2 = __expf(c[2]), e3 = __expf(c[3]);
            suma += e0 + e1;
            sumb += e2 + e3;
            afr[i >> 1][(i & 1) * 2 + 0] = pk_bf16x2(e0, e1);
            afr[i >> 1][(i & 1) * 2 + 1] = pk_bf16x2(e2, e3);
        }
        // stage v(t+1) into other buffer; prefetch v(t+2) + keys(t+1)
        if (t + 1 < NN / NT) {
            const int fi = tid * 2;
            *(uint4*)&s_v[cur ^ 1][(fi >> 3) * VP + (fi & 7) * 8]             = vr0;
            *(uint4*)&s_v[cur ^ 1][((fi + 1) >> 3) * VP + ((fi + 1) & 7) * 8] = vr1;
            if (t + 2 < NN / NT) {
                vr0 = vgb[(t + 2) * 512 + tid * 2];
                vr1 = vgb[(t + 2) * 512 + tid * 2 + 1];
            }
#pragma unroll
            for (int i = 0; i < 8; i++) {
                const int row = ((t + 1) * NT + i * 8 + g8) * ND;
                kf0[i] = kb[row + l4];
                kf1[i] = kb[row + l4 + 4];
            }
        }
        // out GEMM: acc[16m x 64c] += E(16m x 64n) * V(64n x 64c)
#pragma unroll
        for (int kc = 0; kc < 4; kc++) {
            const unsigned a0 = afr[kc][0], a1 = afr[kc][1];
            const unsigned a2 = afr[kc][2], a3 = afr[kc][3];
            const uint32_t rowa = (uint32_t)__cvta_generic_to_shared(
                &s_v[cur][(kc * 16 + (lane & 15)) * VP]);
#pragma unroll
            for (int ct = 0; ct < 8; ct++) {
                unsigned b0, b1;
                ldsm_x2_trans(b0, b1, rowa + ct * 16);
                mma_bf16(acc[ct], a0, a1, a2, a3, b0, b1);
            }
        }
        __syncthreads();   // v(t+1) visible; v(t) consumed
    }

    // ---------------- Z reduction + normalization factors ----------------
    suma += __shfl_xor_sync(0xffffffffu, suma, 1);
    suma += __shfl_xor_sync(0xffffffffu, suma, 2);
    sumb += __shfl_xor_sync(0xffffffffu, sumb, 1);
    sumb += __shfl_xor_sync(0xffffffffu, sumb, 2);
    if (l4 == 0) {
        s_z[att][wm + g8]     = suma;
        s_z[att][wm + g8 + 8] = sumb;
    }
    __syncthreads();
    if (tid < MT) {
        s_f32[tid] = (*g2p) / s_z[0][tid];
        s_f33[tid] = (*g3p) / s_z[1][tid];
    }
    __syncthreads();

    // ---------------- merge atts through smem + epilogue ----------------
    float* s_red = (float*)s_v;          // [64 m][72] fp32 (overlays s_v exactly)
    const float* fs = att ? s_f33 : s_f32;
    const float fa = fs[wm + g8];
    const float fb = fs[wm + g8 + 8];
    if (att == 1) {
#pragma unroll
        for (int ct = 0; ct < 8; ct++) {
            const int c = ct * 8 + 2 * l4;
            *(float2*)&s_red[(wm + g8) * 72 + c]     = make_float2(fa * acc[ct][0], fa * acc[ct][1]);
            *(float2*)&s_red[(wm + g8 + 8) * 72 + c] = make_float2(fb * acc[ct][2], fb * acc[ct][3]);
        }
    }
    __syncthreads();
    if (att == 0) {
#pragma unroll
        for (int ct = 0; ct < 8; ct++) {
            const int c = ct * 8 + 2 * l4;
            float2 lo = *(const float2*)&s_red[(wm + g8) * 72 + c];
            float2 hi = *(const float2*)&s_red[(wm + g8 + 8) * 72 + c];
            lo.x += fa * acc[ct][0]; lo.y += fa * acc[ct][1];
            hi.x += fb * acc[ct][2]; hi.y += fb * acc[ct][3];
            *(float2*)&s_red[(wm + g8) * 72 + c]     = lo;
            *(float2*)&s_red[(wm + g8 + 8) * 72 + c] = hi;
        }
    }
    __syncthreads();
    {
        const float* xb = x + (size_t)b * (2 * NCH) * NN;   // x3 = channels 0..63
        float* ob = out + (size_t)b * NCH * NN;
#pragma unroll
        for (int j = 0; j < 4; j++) {
            const int idx = tid + j * 256;   // 64c x 16 float4-of-m
            const int c   = idx >> 4;
            const int mf  = idx & 15;
            const float4 xv = *(const float4*)(xb + (size_t)c * NN + m0 + mf * 4);
            float4 o;
            o.x = s_red[(mf * 4 + 0) * 72 + c] + xv.x;
            o.y = s_red[(mf * 4 + 1) * 72 + c] + xv.y;
            o.z = s_red[(mf * 4 + 2) * 72 + c] + xv.z;
            o.w = s_red[(mf * 4 + 3) * 72 + c] + xv.w;
            *(float4*)(ob + (size_t)c * NN + m0 + mf * 4) = o;
        }
    }
}

extern "C" void kernel_launch(void* const* d_in, const int* in_sizes, int n_in,
                              void* d_out, int out_size)
{
    const float* x   = (const float*)d_in[0];
    const float* wq2 = (const float*)d_in[1];
    const float* bq2 = (const float*)d_in[2];
    const float* wq3 = (const float*)d_in[3];
    const float* bq3 = (const float*)d_in[4];
    const float* wv3 = (const float*)d_in[5];
    const float* bv3 = (const float*)d_in[6];
    const float* g2  = (const float*)d_in[7];
    const float* g3  = (const float*)d_in[8];
    float* out = (float*)d_out;

    proj_kernel<<<dim3(NN / 128, NB, 2), 128>>>(x, wq2, bq2, wq3, bq3, wv3, bv3);
    att_kernel<<<dim3(NN / MT, NB), 256>>>(x, g2, g3, out);
}

// round 13
// speedup vs baseline: 1.6260x; 1.2193x over previous
#include <cuda_runtime.h>
#include <cuda_bf16.h>
#include <cstdint>

// Problem constants: B=4, C=128, W=H=64
#define NB  4
#define NCH 64
#define ND  8
#define NN  4096
#define MT  64      // query tile -> grid 256
#define NT  64      // key tile
#define VP  72      // v-tile pad (bf16 units)
#define L2E 1.4426950408889634f

// Scratch (no cudaMalloc allowed)
// p2t/p3t layout per token: PERMUTED pairs [d0,d4, d1,d5, d2,d6, d3,d7]
// so mma fragment (l4, l4+4) is one aligned float2 at index l4.
__device__ __align__(16) float         g_p2t[NB * NN * ND];   // tf32-rounded
__device__ __align__(16) float         g_p3t[NB * NN * ND];   // tf32-rounded
__device__ __align__(16) __nv_bfloat16 g_v3b[NB * NN * NCH];  // [b][n][c] bf16

__device__ __forceinline__ float to_tf32(float x) {
    unsigned u;
    asm("cvt.rna.tf32.f32 %0, %1;" : "=r"(u) : "f"(x));
    return __uint_as_float(u);
}
__device__ __forceinline__ float ex2f(float x) {
    float r;
    asm("ex2.approx.f32 %0, %1;" : "=f"(r) : "f"(x));
    return r;
}
__device__ __forceinline__ unsigned pk_bf16x2(float lo, float hi) {
    unsigned r;
    asm("cvt.rn.bf16x2.f32 %0, %1, %2;" : "=r"(r) : "f"(hi), "f"(lo));
    return r;
}
__device__ __forceinline__ void mma_tf32(float* c,
                                         unsigned a0, unsigned a1, unsigned a2, unsigned a3,
                                         unsigned b0, unsigned b1)
{
    asm volatile(
        "mma.sync.aligned.m16n8k8.row.col.f32.tf32.tf32.f32 "
        "{%0,%1,%2,%3}, {%4,%5,%6,%7}, {%8,%9}, {%0,%1,%2,%3};"
        : "+f"(c[0]), "+f"(c[1]), "+f"(c[2]), "+f"(c[3])
        : "r"(a0), "r"(a1), "r"(a2), "r"(a3), "r"(b0), "r"(b1));
}
__device__ __forceinline__ void mma_bf16(float* c,
                                         unsigned a0, unsigned a1, unsigned a2, unsigned a3,
                                         unsigned b0, unsigned b1)
{
    asm volatile(
        "mma.sync.aligned.m16n8k16.row.col.f32.bf16.bf16.f32 "
        "{%0,%1,%2,%3}, {%4,%5,%6,%7}, {%8,%9}, {%0,%1,%2,%3};"
        : "+f"(c[0]), "+f"(c[1]), "+f"(c[2]), "+f"(c[3])
        : "r"(a0), "r"(a1), "r"(a2), "r"(a3), "r"(b0), "r"(b1));
}
__device__ __forceinline__ void ldsm_x4_trans(unsigned& r0, unsigned& r1,
                                              unsigned& r2, unsigned& r3, uint32_t addr)
{
    asm volatile("ldmatrix.sync.aligned.m8n8.x4.trans.shared.b16 {%0,%1,%2,%3}, [%4];"
                 : "=r"(r0), "=r"(r1), "=r"(r2), "=r"(r3) : "r"(addr));
}

// ---------------------------------------------------------------------------
// K1: projections, 3-way z-split. z=0: p2,p3 (tf32, permuted); z=1: v[0:32];
//     z=2: v[32:64] (bf16, packed stores).
// ---------------------------------------------------------------------------
__global__ void proj_kernel(const float* __restrict__ x,
                            const float* __restrict__ wq2, const float* __restrict__ bq2,
                            const float* __restrict__ wq3, const float* __restrict__ bq3,
                            const float* __restrict__ wv3, const float* __restrict__ bv3)
{
    __shared__ float s_wq2[ND * NCH];
    __shared__ float s_wq3[ND * NCH];
    __shared__ float s_wv[32 * NCH];
    __shared__ float s_b[32];

    const int tid = threadIdx.x;
    const int z   = blockIdx.z;
    const int b   = blockIdx.y;
    const int n   = blockIdx.x * 128 + tid;
    const float* xb = x + (size_t)b * (2 * NCH) * NN;

    if (z == 0) {
        for (int i = tid; i < ND * NCH; i += 128) { s_wq2[i] = wq2[i]; s_wq3[i] = wq3[i]; }
        if (tid < ND)           s_b[tid] = bq2[tid];
        else if (tid < 2 * ND)  s_b[tid] = bq3[tid - ND];
        __syncthreads();

        float p2[ND], p3[ND];
#pragma unroll
        for (int d = 0; d < ND; d++) { p2[d] = s_b[d]; p3[d] = s_b[ND + d]; }
        for (int c = 0; c < NCH; c++) {
            const float x3v = xb[c * NN + n];
            const float x2v = xb[(NCH + c) * NN + n];
#pragma unroll
            for (int d = 0; d < ND; d++) {
                p2[d] = fmaf(s_wq2[d * NCH + c], x2v, p2[d]);
                p3[d] = fmaf(s_wq3[d * NCH + c], x3v, p3[d]);
            }
        }
        float* o2 = g_p2t + ((size_t)b * NN + n) * ND;
        float* o3 = g_p3t + ((size_t)b * NN + n) * ND;
#pragma unroll
        for (int d = 0; d < 4; d++) {            // permuted pair layout
            o2[2 * d]     = to_tf32(p2[d]);
            o2[2 * d + 1] = to_tf32(p2[d + 4]);
            o3[2 * d]     = to_tf32(p3[d]);
            o3[2 * d + 1] = to_tf32(p3[d + 4]);
        }
    } else {
        const int co0 = (z - 1) * 32;
        for (int i = tid; i < 32 * NCH; i += 128) s_wv[i] = wv3[co0 * NCH + i];
        if (tid < 32) s_b[tid] = bv3[co0 + tid];
        __syncthreads();

        float v[32];
#pragma unroll
        for (int c = 0; c < 32; c++) v[c] = s_b[c];
        for (int c = 0; c < NCH; c++) {
            const float x3v = xb[c * NN + n];
#pragma unroll
            for (int o = 0; o < 32; o++)
                v[o] = fmaf(s_wv[o * NCH + c], x3v, v[o]);
        }
        unsigned* ov = (unsigned*)(g_v3b + ((size_t)b * NN + n) * NCH + co0);
#pragma unroll
        for (int c = 0; c < 32; c += 2) ov[c >> 1] = pk_bf16x2(v[c], v[c + 1]);
    }
}

// ---------------------------------------------------------------------------
// K2: single-pass dual attention per (batch, 64-query tile). 256 threads.
//  Warp w: wm = (w&3)*16 (m-block); att = w>>2 (0: att32/p2-keys, 1: att33/p3).
//  q A-frag pre-scaled by log2(e) so exp = ex2.approx directly.
//  Per tile: 8 tf32 score mmas -> ex2 -> register A-frags -> bf16 out-GEMM
//  (ldmatrix.x4). One sync/tile (v double-buffered). Atts merged at end.
// ---------------------------------------------------------------------------
__global__ __launch_bounds__(256, 2) void att_kernel(const float* __restrict__ x,
                                                     const float* __restrict__ g2p,
                                                     const float* __restrict__ g3p,
                                                     float* __restrict__ out)
{
    __shared__ __align__(16) __nv_bfloat16 s_v[2][NT * VP];   // 18432B; aliased s_red
    __shared__ __align__(16) float s_z[2][MT];
    __shared__ __align__(16) float s_f32[MT];
    __shared__ __align__(16) float s_f33[MT];

    const int tid  = threadIdx.x;
    const int b    = blockIdx.y;
    const int m0   = blockIdx.x * MT;
    const int warp = tid >> 5;
    const int lane = tid & 31;
    const int g8   = lane >> 2;
    const int l4   = lane & 3;
    const int wm   = (warp & 3) * 16;
    const int att  = warp >> 2;         // 0: att32, 1: att33

    const float* pb2 = g_p2t + (size_t)b * NN * ND;
    const float* pb3 = g_p3t + (size_t)b * NN * ND;
    const float* kb  = att ? pb3 : pb2; // this warp's key projection
    const uint4* vgb = (const uint4*)(g_v3b + (size_t)b * NN * NCH);

    // q A-fragment (permuted pair layout; pre-scaled by log2 e)
    const float* qb = pb3 + (size_t)m0 * ND;
    const float2 qva = ((const float2*)(qb + (wm + g8) * ND))[l4];
    const float2 qvb = ((const float2*)(qb + (wm + g8 + 8) * ND))[l4];
    const unsigned aq0 = __float_as_uint(qva.x * L2E);
    const unsigned aq1 = __float_as_uint(qvb.x * L2E);
    const unsigned aq2 = __float_as_uint(qva.y * L2E);
    const unsigned aq3 = __float_as_uint(qvb.y * L2E);

    float acc[8][4];                    // 16m x 64c for this warp's att
#pragma unroll
    for (int ct = 0; ct < 8; ct++)
#pragma unroll
        for (int j = 0; j < 4; j++) acc[ct][j] = 0.f;
    float suma = 0.f, sumb = 0.f;       // row sums (rows g8 / g8+8)

    // preamble: stage v(0), prefetch v(1) + keys(0)
    uint4 vr0 = vgb[tid * 2];
    uint4 vr1 = vgb[tid * 2 + 1];
    {
        const int fi = tid * 2;
        *(uint4*)&s_v[0][(fi >> 3) * VP + (fi & 7) * 8]             = vr0;
        *(uint4*)&s_v[0][((fi + 1) >> 3) * VP + ((fi + 1) & 7) * 8] = vr1;
    }
    vr0 = vgb[512 + tid * 2];
    vr1 = vgb[512 + tid * 2 + 1];
    float2 kf[8];
#pragma unroll
    for (int i = 0; i < 8; i++)
        kf[i] = ((const float2*)(kb + (i * 8 + g8) * ND))[l4];
    __syncthreads();

    for (int t = 0; t < NN / NT; t++) {
        const int cur = t & 1;
        // scores over all 64 keys -> ex2 -> register A-fragments
        unsigned afr[4][4];
#pragma unroll
        for (int i = 0; i < 8; i++) {
            float c[4] = {0.f, 0.f, 0.f, 0.f};
            mma_tf32(c, aq0, aq1, aq2, aq3,
                     __float_as_uint(kf[i].x), __float_as_uint(kf[i].y));
            const float e0 = ex2f(c[0]), e1 = ex2f(c[1]);
            const float e2 = ex2f(c[2]), e3 = ex2f(c[3]);
            suma += e0 + e1;
            sumb += e2 + e3;
            afr[i >> 1][(i & 1) * 2 + 0] = pk_bf16x2(e0, e1);
            afr[i >> 1][(i & 1) * 2 + 1] = pk_bf16x2(e2, e3);
        }
        // stage v(t+1) into other buffer; prefetch v(t+2) + keys(t+1)
        if (t + 1 < NN / NT) {
            const int fi = tid * 2;
            *(uint4*)&s_v[cur ^ 1][(fi >> 3) * VP + (fi & 7) * 8]             = vr0;
            *(uint4*)&s_v[cur ^ 1][((fi + 1) >> 3) * VP + ((fi + 1) & 7) * 8] = vr1;
            if (t + 2 < NN / NT) {
                vr0 = vgb[(t + 2) * 512 + tid * 2];
                vr1 = vgb[(t + 2) * 512 + tid * 2 + 1];
            }
#pragma unroll
            for (int i = 0; i < 8; i++)
                kf[i] = ((const float2*)(kb + ((t + 1) * NT + i * 8 + g8) * ND))[l4];
        }
        // out GEMM: acc[16m x 64c] += E(16m x 64n) * V(64n x 64c)
#pragma unroll
        for (int kc = 0; kc < 4; kc++) {
            const unsigned a0 = afr[kc][0], a1 = afr[kc][1];
            const unsigned a2 = afr[kc][2], a3 = afr[kc][3];
            const uint32_t rowa = (uint32_t)__cvta_generic_to_shared(
                &s_v[cur][(kc * 16 + (lane & 15)) * VP + ((lane >> 4) << 3)]);
#pragma unroll
            for (int ct = 0; ct < 4; ct++) {
                unsigned b0, b1, b2, b3;
                ldsm_x4_trans(b0, b1, b2, b3, rowa + ct * 32);
                mma_bf16(acc[2 * ct],     a0, a1, a2, a3, b0, b1);
                mma_bf16(acc[2 * ct + 1], a0, a1, a2, a3, b2, b3);
            }
        }
        __syncthreads();   // v(t+1) visible; v(t) consumed
    }

    // ---------------- Z reduction + normalization factors ----------------
    suma += __shfl_xor_sync(0xffffffffu, suma, 1);
    suma += __shfl_xor_sync(0xffffffffu, suma, 2);
    sumb += __shfl_xor_sync(0xffffffffu, sumb, 1);
    sumb += __shfl_xor_sync(0xffffffffu, sumb, 2);
    if (l4 == 0) {
        s_z[att][wm + g8]     = suma;
        s_z[att][wm + g8 + 8] = sumb;
    }
    __syncthreads();
    if (tid < MT) {
        s_f32[tid] = (*g2p) / s_z[0][tid];
        s_f33[tid] = (*g3p) / s_z[1][tid];
    }
    __syncthreads();

    // ---------------- merge atts through smem + epilogue ----------------
    float* s_red = (float*)s_v;          // [64 m][72] fp32 (overlays s_v exactly)
    const float* fs = att ? s_f33 : s_f32;
    const float fa = fs[wm + g8];
    const float fb = fs[wm + g8 + 8];
    if (att == 1) {
#pragma unroll
        for (int ct = 0; ct < 8; ct++) {
            const int c = ct * 8 + 2 * l4;
            *(float2*)&s_red[(wm + g8) * 72 + c]     = make_float2(fa * acc[ct][0], fa * acc[ct][1]);
            *(float2*)&s_red[(wm + g8 + 8) * 72 + c] = make_float2(fb * acc[ct][2], fb * acc[ct][3]);
        }
    }
    __syncthreads();
    if (att == 0) {
#pragma unroll
        for (int ct = 0; ct < 8; ct++) {
            const int c = ct * 8 + 2 * l4;
            float2 lo = *(const float2*)&s_red[(wm + g8) * 72 + c];
            float2 hi = *(const float2*)&s_red[(wm + g8 + 8) * 72 + c];
            lo.x += fa * acc[ct][0]; lo.y += fa * acc[ct][1];
            hi.x += fb * acc[ct][2]; hi.y += fb * acc[ct][3];
            *(float2*)&s_red[(wm + g8) * 72 + c]     = lo;
            *(float2*)&s_red[(wm + g8 + 8) * 72 + c] = hi;
        }
    }
    __syncthreads();
    {
        const float* xb = x + (size_t)b * (2 * NCH) * NN;   // x3 = channels 0..63
        float* ob = out + (size_t)b * NCH * NN;
#pragma unroll
        for (int j = 0; j < 4; j++) {
            const int idx = tid + j * 256;   // 64c x 16 float4-of-m
            const int c   = idx >> 4;
            const int mf  = idx & 15;
            const float4 xv = *(const float4*)(xb + (size_t)c * NN + m0 + mf * 4);
            float4 o;
            o.x = s_red[(mf * 4 + 0) * 72 + c] + xv.x;
            o.y = s_red[(mf * 4 + 1) * 72 + c] + xv.y;
            o.z = s_red[(mf * 4 + 2) * 72 + c] + xv.z;
            o.w = s_red[(mf * 4 + 3) * 72 + c] + xv.w;
            *(float4*)(ob + (size_t)c * NN + m0 + mf * 4) = o;
        }
    }
}

extern "C" void kernel_launch(void* const* d_in, const int* in_sizes, int n_in,
                              void* d_out, int out_size)
{
    const float* x   = (const float*)d_in[0];
    const float* wq2 = (const float*)d_in[1];
    const float* bq2 = (const float*)d_in[2];
    const float* wq3 = (const float*)d_in[3];
    const float* bq3 = (const float*)d_in[4];
    const float* wv3 = (const float*)d_in[5];
    const float* bv3 = (const float*)d_in[6];
    const float* g2  = (const float*)d_in[7];
    const float* g3  = (const float*)d_in[8];
    float* out = (float*)d_out;

    proj_kernel<<<dim3(NN / 128, NB, 3), 128>>>(x, wq2, bq2, wq3, bq3, wv3, bv3);
    att_kernel<<<dim3(NN / MT, NB), 256>>>(x, g2, g3, out);
}